// round 9
// baseline (speedup 1.0000x reference)
#include <cuda_runtime.h>
#include <cuda_fp16.h>
#include <cstdint>

#define N_NODES 10000
#define N_EDGES 640000
#define DDIM    128
#define STRIDE  192          // bucket capacity per node (deg~Poisson(64))

// Scratch (allocation-free rule: __device__ globals)
__device__ int    g_cnt [N_NODES];
__device__ int    g_esrc[(size_t)N_NODES * STRIDE];   // srcs bucketed by dst
__device__ __half g_hs  [(size_t)N_NODES * DDIM];     // (x@W)*dinv[row], fp16
__device__ int    g_is64;

// ---------------------------------------------------------------------------
// K1: zero counts + probe adj dtype (int64 node ids have high word 0).
__global__ void k_init(const void* __restrict__ adj, int n) {
    int i = blockIdx.x * blockDim.x + threadIdx.x;
    if (i < n) g_cnt[i] = 0;
    if (i == 0) {
        const long long* a = (const long long*)adj;
        int is64 = 1;
        for (int k = 0; k < 64; k++) {
            long long v = a[k];
            if (v < 0 || v > (long long)N_NODES) { is64 = 0; break; }
        }
        g_is64 = is64;
    }
}

// K2: bucket scatter — 2 edges per thread, paired index loads.
__global__ void k_scatter(const void* __restrict__ adj, int e) {
    int i = (blockIdx.x * blockDim.x + threadIdx.x) * 2;
    if (i >= e) return;

    int s0, s1, d0, d1;
    if (g_is64) {
        const long long* a = (const long long*)adj;
        longlong2 sp = *(const longlong2*)(a + i);
        longlong2 dp = *(const longlong2*)(a + e + i);
        s0 = (int)sp.x; s1 = (int)sp.y;
        d0 = (int)dp.x; d1 = (int)dp.y;
    } else {
        const int* a = (const int*)adj;
        int2 sp = *(const int2*)(a + i);
        int2 dp = *(const int2*)(a + e + i);
        s0 = sp.x; s1 = sp.y;
        d0 = dp.x; d1 = dp.y;
    }

    int p0 = atomicAdd(&g_cnt[d0], 1);
    g_esrc[(size_t)d0 * STRIDE + p0] = s0;
    if (i + 1 < e) {
        int p1 = atomicAdd(&g_cnt[d1], 1);
        g_esrc[(size_t)d1 * STRIDE + p1] = s1;
    }
}

// ---------------------------------------------------------------------------
// K3: hs = fp16( (x @ W) * rsqrt(deg+1) ).
// Occupancy-first tile: 8 rows x 128 cols, 256 threads, thread = 1 row x 4
// cols. Grid = 1250 -> 10000 warps (~100% of chip warp slots). W rows via
// LDG.128; W stays L1-resident per SM (blocks share L1). x tile: broadcast LDS.
__global__ void __launch_bounds__(256) k_gemm(const float* __restrict__ x,
                                              const float* __restrict__ W,
                                              int n) {
    __shared__ float xs[8 * DDIM];
    const int block_row = blockIdx.x * 8;
    const int t = threadIdx.x;

    // load 8x128 x-tile (float4, coalesced); guard only the last block
    {
        const float4* xg = (const float4*)(x + (size_t)block_row * DDIM);
        float4* xs4 = (float4*)xs;
        int limit = (n - block_row) * 32;           // float4s available
        xs4[t] = (t < limit) ? xg[t] : make_float4(0.f, 0.f, 0.f, 0.f);
    }
    __syncthreads();

    const int colg = (t & 31) * 4;                  // 4 consecutive cols
    const int r    = (t >> 5);                      // 1 row per thread

    float a0 = 0.f, a1 = 0.f, a2 = 0.f, a3 = 0.f;

#pragma unroll 8
    for (int k = 0; k < DDIM; k++) {
        float4 w = *(const float4*)(W + (size_t)k * DDIM + colg);
        float xv = xs[r * DDIM + k];                // warp-broadcast LDS
        a0 += xv * w.x;
        a1 += xv * w.y;
        a2 += xv * w.z;
        a3 += xv * w.w;
    }

    int row = block_row + r;
    if (row < n) {
        float di = rsqrtf((float)(g_cnt[row] + 1));
        __half2 h0 = __floats2half2_rn(a0 * di, a1 * di);
        __half2 h1 = __floats2half2_rn(a2 * di, a3 * di);
        uint2 v;
        v.x = *(unsigned*)&h0;
        v.y = *(unsigned*)&h1;
        *(uint2*)(g_hs + (size_t)row * DDIM + colg) = v;
    }
}

// ---------------------------------------------------------------------------
__device__ __forceinline__ void acc_add(float4& a, uint2 v) {
    __half2 p0 = *(__half2*)&v.x;
    __half2 p1 = *(__half2*)&v.y;
    float2 f0 = __half22float2(p0);
    float2 f1 = __half22float2(p1);
    a.x += f0.x; a.y += f0.y; a.z += f1.x; a.w += f1.y;
}

// K4: per-node gather. One warp per node; lane owns 4 cols (8B fp16 load).
//   out[d] = b + dinv[d] * (hs[d] + sum_{s in bucket(d)} hs[s]).  NO atomics.
__global__ void k_gather(const float* __restrict__ b, float* __restrict__ out,
                         int n) {
    int w    = (blockIdx.x * blockDim.x + threadIdx.x) >> 5;
    int lane = threadIdx.x & 31;
    if (w >= n) return;

    const uint2* hs  = (const uint2*)g_hs;          // 32 uint2 per row
    const int*   row = g_esrc + (size_t)w * STRIDE;
    int deg = g_cnt[w];

    float4 acc = make_float4(0.f, 0.f, 0.f, 0.f);
    acc_add(acc, hs[(size_t)w * 32 + lane]);        // self-loop term

    for (int k = 0; k < deg; k += 32) {
        int s_l = (k + lane < deg) ? row[k + lane] : -1;
#pragma unroll
        for (int j = 0; j < 32; j++) {
            int s = __shfl_sync(0xffffffffu, s_l, j);   // uniform across warp
            if (s < 0) break;
            acc_add(acc, hs[(size_t)s * 32 + lane]);
        }
    }

    float di = rsqrtf((float)(deg + 1));
    float4 bb = ((const float4*)b)[lane];
    float4 o = make_float4(bb.x + di * acc.x, bb.y + di * acc.y,
                           bb.z + di * acc.z, bb.w + di * acc.w);
    ((float4*)out)[(size_t)w * 32 + lane] = o;
}

// ---------------------------------------------------------------------------
extern "C" void kernel_launch(void* const* d_in, const int* in_sizes, int n_in,
                              void* d_out, int out_size) {
    const float* x   = (const float*)d_in[0];
    const void*  adj = (const void*)d_in[1];
    const float* W   = (const float*)d_in[2];
    const float* b   = (const float*)d_in[3];
    float*       out = (float*)d_out;

    int n = in_sizes[0] / DDIM;   // 10000
    int e = in_sizes[1] / 2;      // 640000

    k_init   <<<(n + 255) / 256, 256>>>(adj, n);
    int pairs = (e + 1) / 2;
    k_scatter<<<(pairs + 255) / 256, 256>>>(adj, e);
    k_gemm   <<<(n + 7) / 8, 256>>>(x, W, n);

    long long threads_needed = (long long)n * 32;   // one warp per node
    int blocks = (int)((threads_needed + 255) / 256);
    k_gather <<<blocks, 256>>>(b, out, n);
}

// round 10
// speedup vs baseline: 1.3199x; 1.3199x over previous
#include <cuda_runtime.h>
#include <cuda_fp16.h>
#include <cstdint>

#define N_NODES 10000
#define N_EDGES 640000
#define DDIM    128
#define STRIDE  192          // bucket capacity per node (deg~Poisson(64))

// Scratch (allocation-free rule: __device__ globals)
__device__ int    g_cnt [N_NODES];
__device__ int    g_esrc[(size_t)N_NODES * STRIDE];   // srcs bucketed by dst
__device__ __half g_hs  [(size_t)N_NODES * DDIM];     // (x@W)*dinv[row], fp16
__device__ int    g_is64;

// ---------------------------------------------------------------------------
// K1: zero counts + probe adj dtype (int64 node ids have high word 0).
__global__ void k_init(const void* __restrict__ adj, int n) {
    int i = blockIdx.x * blockDim.x + threadIdx.x;
    if (i < n) g_cnt[i] = 0;
    if (i == 0) {
        const long long* a = (const long long*)adj;
        int is64 = 1;
        for (int k = 0; k < 64; k++) {
            long long v = a[k];
            if (v < 0 || v > (long long)N_NODES) { is64 = 0; break; }
        }
        g_is64 = is64;
    }
}

// K2: bucket scatter — 2 edges per thread, paired index loads.
__global__ void k_scatter(const void* __restrict__ adj, int e) {
    int i = (blockIdx.x * blockDim.x + threadIdx.x) * 2;
    if (i >= e) return;

    int s0, s1, d0, d1;
    if (g_is64) {
        const long long* a = (const long long*)adj;
        longlong2 sp = *(const longlong2*)(a + i);
        longlong2 dp = *(const longlong2*)(a + e + i);
        s0 = (int)sp.x; s1 = (int)sp.y;
        d0 = (int)dp.x; d1 = (int)dp.y;
    } else {
        const int* a = (const int*)adj;
        int2 sp = *(const int2*)(a + i);
        int2 dp = *(const int2*)(a + e + i);
        s0 = sp.x; s1 = sp.y;
        d0 = dp.x; d1 = dp.y;
    }

    int p0 = atomicAdd(&g_cnt[d0], 1);
    g_esrc[(size_t)d0 * STRIDE + p0] = s0;
    if (i + 1 < e) {
        int p1 = atomicAdd(&g_cnt[d1], 1);
        g_esrc[(size_t)d1 * STRIDE + p1] = s1;
    }
}

// ---------------------------------------------------------------------------
// K3: hs = fp16( (x @ W) * rsqrt(deg+1) ).
// Balanced tile: 8 rows x 128 cols per block, 128 threads, thread = 2 rows x
// 4 cols. Grid = 1250 -> ~8 blocks/SM, 5000 warps (occ ~53%). 2-row W reuse
// keeps the per-SM W L1 traffic at ~10us floor (R9 failure: 1 row/thread ->
// 4.4MB W through L1 per SM, ~20us floor; R8: 4 rows -> occ 25%, latency-bound).
__global__ void __launch_bounds__(128) k_gemm(const float* __restrict__ x,
                                              const float* __restrict__ W,
                                              int n) {
    __shared__ float xs[8 * DDIM];
    const int block_row = blockIdx.x * 8;
    const int t = threadIdx.x;

    // load 8x128 x-tile (256 float4, 128 threads x 2); guard only last block
    {
        const float4* xg = (const float4*)(x + (size_t)block_row * DDIM);
        float4* xs4 = (float4*)xs;
        int limit = (n - block_row) * 32;           // float4s available
#pragma unroll
        for (int i = 0; i < 2; i++) {
            int idx = t + i * 128;
            xs4[idx] = (idx < limit) ? xg[idx]
                                     : make_float4(0.f, 0.f, 0.f, 0.f);
        }
    }
    __syncthreads();

    const int colg  = (t & 31) * 4;                 // 4 consecutive cols
    const int rbase = (t >> 5) * 2;                 // 2 rows per thread

    float a0[4], a1[4];
#pragma unroll
    for (int c = 0; c < 4; c++) { a0[c] = 0.f; a1[c] = 0.f; }

#pragma unroll 8
    for (int k = 0; k < DDIM; k++) {
        float4 w = *(const float4*)(W + (size_t)k * DDIM + colg);
        float x0 = xs[rbase * DDIM + k];            // warp-broadcast LDS
        float x1 = xs[(rbase + 1) * DDIM + k];
        a0[0] += x0 * w.x;  a1[0] += x1 * w.x;
        a0[1] += x0 * w.y;  a1[1] += x1 * w.y;
        a0[2] += x0 * w.z;  a1[2] += x1 * w.z;
        a0[3] += x0 * w.w;  a1[3] += x1 * w.w;
    }

#pragma unroll
    for (int r = 0; r < 2; r++) {
        int row = block_row + rbase + r;
        if (row < n) {
            float di = rsqrtf((float)(g_cnt[row] + 1));
            float* a = (r == 0) ? a0 : a1;
            __half2 h0 = __floats2half2_rn(a[0] * di, a[1] * di);
            __half2 h1 = __floats2half2_rn(a[2] * di, a[3] * di);
            uint2 v;
            v.x = *(unsigned*)&h0;
            v.y = *(unsigned*)&h1;
            *(uint2*)(g_hs + (size_t)row * DDIM + colg) = v;
        }
    }
}

// ---------------------------------------------------------------------------
__device__ __forceinline__ void acc_add(float4& a, uint2 v) {
    __half2 p0 = *(__half2*)&v.x;
    __half2 p1 = *(__half2*)&v.y;
    float2 f0 = __half22float2(p0);
    float2 f1 = __half22float2(p1);
    a.x += f0.x; a.y += f0.y; a.z += f1.x; a.w += f1.y;
}

// K4: per-node gather. One warp per node; lane owns 4 cols (8B fp16 load).
//   out[d] = b + dinv[d] * (hs[d] + sum_{s in bucket(d)} hs[s]).  NO atomics.
__global__ void k_gather(const float* __restrict__ b, float* __restrict__ out,
                         int n) {
    int w    = (blockIdx.x * blockDim.x + threadIdx.x) >> 5;
    int lane = threadIdx.x & 31;
    if (w >= n) return;

    const uint2* hs  = (const uint2*)g_hs;          // 32 uint2 per row
    const int*   row = g_esrc + (size_t)w * STRIDE;
    int deg = g_cnt[w];

    float4 acc = make_float4(0.f, 0.f, 0.f, 0.f);
    acc_add(acc, hs[(size_t)w * 32 + lane]);        // self-loop term

    for (int k = 0; k < deg; k += 32) {
        int s_l = (k + lane < deg) ? row[k + lane] : -1;
#pragma unroll
        for (int j = 0; j < 32; j++) {
            int s = __shfl_sync(0xffffffffu, s_l, j);   // uniform across warp
            if (s < 0) break;
            acc_add(acc, hs[(size_t)s * 32 + lane]);
        }
    }

    float di = rsqrtf((float)(deg + 1));
    float4 bb = ((const float4*)b)[lane];
    float4 o = make_float4(bb.x + di * acc.x, bb.y + di * acc.y,
                           bb.z + di * acc.z, bb.w + di * acc.w);
    ((float4*)out)[(size_t)w * 32 + lane] = o;
}

// ---------------------------------------------------------------------------
extern "C" void kernel_launch(void* const* d_in, const int* in_sizes, int n_in,
                              void* d_out, int out_size) {
    const float* x   = (const float*)d_in[0];
    const void*  adj = (const void*)d_in[1];
    const float* W   = (const float*)d_in[2];
    const float* b   = (const float*)d_in[3];
    float*       out = (float*)d_out;

    int n = in_sizes[0] / DDIM;   // 10000
    int e = in_sizes[1] / 2;      // 640000

    k_init   <<<(n + 255) / 256, 256>>>(adj, n);
    int pairs = (e + 1) / 2;
    k_scatter<<<(pairs + 255) / 256, 256>>>(adj, e);
    k_gemm   <<<(n + 7) / 8, 128>>>(x, W, n);

    long long threads_needed = (long long)n * 32;   // one warp per node
    int blocks = (int)((threads_needed + 255) / 256);
    k_gather <<<blocks, 256>>>(b, out, n);
}

// round 11
// speedup vs baseline: 1.7382x; 1.3169x over previous
#include <cuda_runtime.h>
#include <cuda_fp16.h>
#include <cstdint>

#define N_NODES 10000
#define N_EDGES 640000
#define DDIM    128
#define STRIDE  192          // bucket capacity per node (deg~Poisson(64))

// Scratch (allocation-free rule: __device__ globals)
__device__ int    g_cnt [N_NODES];
__device__ int    g_esrc[(size_t)N_NODES * STRIDE];   // srcs bucketed by dst
__device__ __half g_hs  [(size_t)N_NODES * DDIM];     // (x@W)*dinv[row], fp16
__device__ int    g_is64;

// ---------------------------------------------------------------------------
// K1: zero counts + probe adj dtype (int64 node ids have high word 0).
__global__ void k_init(const void* __restrict__ adj, int n) {
    int i = blockIdx.x * blockDim.x + threadIdx.x;
    if (i < n) g_cnt[i] = 0;
    if (i == 0) {
        const long long* a = (const long long*)adj;
        int is64 = 1;
        for (int k = 0; k < 64; k++) {
            long long v = a[k];
            if (v < 0 || v > (long long)N_NODES) { is64 = 0; break; }
        }
        g_is64 = is64;
    }
}

// K2: bucket scatter — 2 edges per thread, paired index loads.
__global__ void k_scatter(const void* __restrict__ adj, int e) {
    int i = (blockIdx.x * blockDim.x + threadIdx.x) * 2;
    if (i >= e) return;

    int s0, s1, d0, d1;
    if (g_is64) {
        const long long* a = (const long long*)adj;
        longlong2 sp = *(const longlong2*)(a + i);
        longlong2 dp = *(const longlong2*)(a + e + i);
        s0 = (int)sp.x; s1 = (int)sp.y;
        d0 = (int)dp.x; d1 = (int)dp.y;
    } else {
        const int* a = (const int*)adj;
        int2 sp = *(const int2*)(a + i);
        int2 dp = *(const int2*)(a + e + i);
        s0 = sp.x; s1 = sp.y;
        d0 = dp.x; d1 = dp.y;
    }

    int p0 = atomicAdd(&g_cnt[d0], 1);
    g_esrc[(size_t)d0 * STRIDE + p0] = s0;
    if (i + 1 < e) {
        int p1 = atomicAdd(&g_cnt[d1], 1);
        g_esrc[(size_t)d1 * STRIDE + p1] = s1;
    }
}

// ---------------------------------------------------------------------------
// K3: hs = fp16( (x @ W) * rsqrt(deg+1) ).
// Tile: 8 rows x 128 cols, 128 threads, thread = 2 rows x 4 cols.
// Grid 1250, ~8 blocks/SM (proven R10 config).
__global__ void __launch_bounds__(128) k_gemm(const float* __restrict__ x,
                                              const float* __restrict__ W,
                                              int n) {
    __shared__ float xs[8 * DDIM];
    const int block_row = blockIdx.x * 8;
    const int t = threadIdx.x;

    {
        const float4* xg = (const float4*)(x + (size_t)block_row * DDIM);
        float4* xs4 = (float4*)xs;
        int limit = (n - block_row) * 32;
#pragma unroll
        for (int i = 0; i < 2; i++) {
            int idx = t + i * 128;
            xs4[idx] = (idx < limit) ? xg[idx]
                                     : make_float4(0.f, 0.f, 0.f, 0.f);
        }
    }
    __syncthreads();

    const int colg  = (t & 31) * 4;
    const int rbase = (t >> 5) * 2;

    float a0[4], a1[4];
#pragma unroll
    for (int c = 0; c < 4; c++) { a0[c] = 0.f; a1[c] = 0.f; }

#pragma unroll 8
    for (int k = 0; k < DDIM; k++) {
        float4 w = *(const float4*)(W + (size_t)k * DDIM + colg);
        float x0 = xs[rbase * DDIM + k];
        float x1 = xs[(rbase + 1) * DDIM + k];
        a0[0] += x0 * w.x;  a1[0] += x1 * w.x;
        a0[1] += x0 * w.y;  a1[1] += x1 * w.y;
        a0[2] += x0 * w.z;  a1[2] += x1 * w.z;
        a0[3] += x0 * w.w;  a1[3] += x1 * w.w;
    }

#pragma unroll
    for (int r = 0; r < 2; r++) {
        int row = block_row + rbase + r;
        if (row < n) {
            float di = rsqrtf((float)(g_cnt[row] + 1));
            float* a = (r == 0) ? a0 : a1;
            __half2 h0 = __floats2half2_rn(a[0] * di, a[1] * di);
            __half2 h1 = __floats2half2_rn(a[2] * di, a[3] * di);
            uint2 v;
            v.x = *(unsigned*)&h0;
            v.y = *(unsigned*)&h1;
            *(uint2*)(g_hs + (size_t)row * DDIM + colg) = v;
        }
    }
}

// ---------------------------------------------------------------------------
__device__ __forceinline__ __half2 u2h(unsigned u) { return *(__half2*)&u; }

__device__ __forceinline__ void acc_add(float4& a, uint2 v) {
    float2 f0 = __half22float2(u2h(v.x));
    float2 f1 = __half22float2(u2h(v.y));
    a.x += f0.x; a.y += f0.y; a.z += f1.x; a.w += f1.y;
}

// K4: per-node gather, instruction-diet version.
// One warp per node; lane owns 4 cols (8B fp16 load).
// 8-edge chunks: 2 uniform LDG.128 index loads, 8 scattered LDG.64 data
// loads (MLP=8), pairwise HADD2 tree (14 ops), fold to fp32 once per chunk.
// ~5 warp-instr/edge vs R10's ~13 (R10 was issue-bound: issue=52%, DRAM=2%).
__global__ void k_gather(const float* __restrict__ b, float* __restrict__ out,
                         int n) {
    int w    = (blockIdx.x * blockDim.x + threadIdx.x) >> 5;
    int lane = threadIdx.x & 31;
    if (w >= n) return;

    const uint2* hs  = (const uint2*)g_hs;          // 32 uint2 per row
    const int*   row = g_esrc + (size_t)w * STRIDE; // 16B-aligned (192*4)
    int deg = g_cnt[w];

    float4 acc = make_float4(0.f, 0.f, 0.f, 0.f);
    acc_add(acc, hs[(size_t)w * 32 + lane]);        // self-loop term

    int kmain = deg & ~7;
    for (int k = 0; k < kmain; k += 8) {
        int4 i0 = *(const int4*)(row + k);          // uniform broadcast
        int4 i1 = *(const int4*)(row + k + 4);

        uint2 v0 = hs[(size_t)i0.x * 32 + lane];
        uint2 v1 = hs[(size_t)i0.y * 32 + lane];
        uint2 v2 = hs[(size_t)i0.z * 32 + lane];
        uint2 v3 = hs[(size_t)i0.w * 32 + lane];
        uint2 v4 = hs[(size_t)i1.x * 32 + lane];
        uint2 v5 = hs[(size_t)i1.y * 32 + lane];
        uint2 v6 = hs[(size_t)i1.z * 32 + lane];
        uint2 v7 = hs[(size_t)i1.w * 32 + lane];

        // pairwise fp16 tree, low half (cols 0-1)
        __half2 l01 = __hadd2(u2h(v0.x), u2h(v1.x));
        __half2 l23 = __hadd2(u2h(v2.x), u2h(v3.x));
        __half2 l45 = __hadd2(u2h(v4.x), u2h(v5.x));
        __half2 l67 = __hadd2(u2h(v6.x), u2h(v7.x));
        __half2 lo  = __hadd2(__hadd2(l01, l23), __hadd2(l45, l67));
        // high half (cols 2-3)
        __half2 h01 = __hadd2(u2h(v0.y), u2h(v1.y));
        __half2 h23 = __hadd2(u2h(v2.y), u2h(v3.y));
        __half2 h45 = __hadd2(u2h(v4.y), u2h(v5.y));
        __half2 h67 = __hadd2(u2h(v6.y), u2h(v7.y));
        __half2 hi  = __hadd2(__hadd2(h01, h23), __hadd2(h45, h67));

        float2 fl = __half22float2(lo);
        float2 fh = __half22float2(hi);
        acc.x += fl.x; acc.y += fl.y; acc.z += fh.x; acc.w += fh.y;
    }

    for (int k = kmain; k < deg; k++) {             // tail <8, fp32 path
        int s = row[k];
        acc_add(acc, hs[(size_t)s * 32 + lane]);
    }

    float di = rsqrtf((float)(deg + 1));
    float4 bb = ((const float4*)b)[lane];
    float4 o = make_float4(bb.x + di * acc.x, bb.y + di * acc.y,
                           bb.z + di * acc.z, bb.w + di * acc.w);
    ((float4*)out)[(size_t)w * 32 + lane] = o;
}

// ---------------------------------------------------------------------------
extern "C" void kernel_launch(void* const* d_in, const int* in_sizes, int n_in,
                              void* d_out, int out_size) {
    const float* x   = (const float*)d_in[0];
    const void*  adj = (const void*)d_in[1];
    const float* W   = (const float*)d_in[2];
    const float* b   = (const float*)d_in[3];
    float*       out = (float*)d_out;

    int n = in_sizes[0] / DDIM;   // 10000
    int e = in_sizes[1] / 2;      // 640000

    k_init   <<<(n + 255) / 256, 256>>>(adj, n);
    int pairs = (e + 1) / 2;
    k_scatter<<<(pairs + 255) / 256, 256>>>(adj, e);
    k_gemm   <<<(n + 7) / 8, 128>>>(x, W, n);

    long long threads_needed = (long long)n * 32;   // one warp per node
    int blocks = (int)((threads_needed + 255) / 256);
    k_gather <<<blocks, 256>>>(b, out, n);
}

// round 12
// speedup vs baseline: 1.9201x; 1.1047x over previous
#include <cuda_runtime.h>
#include <cuda_fp16.h>
#include <mma.h>
#include <cstdint>

using namespace nvcuda;

#define N_NODES 10000
#define N_EDGES 640000
#define DDIM    128
#define STRIDE  192          // bucket capacity per node (deg~Poisson(64))
#define GM_ROWS 32           // gemm block tile rows
#define LDH     136          // smem leading dim (halfs), 8-half padded

// Scratch (allocation-free rule: __device__ globals)
__device__ int    g_cnt [N_NODES];
__device__ int    g_esrc[(size_t)N_NODES * STRIDE];   // srcs bucketed by dst
__device__ __half g_hs  [(size_t)N_NODES * DDIM];     // (x@W)*dinv[row], fp16
__device__ int    g_is64;

// ---------------------------------------------------------------------------
// K1: zero counts + probe adj dtype (int64 node ids have high word 0).
__global__ void k_init(const void* __restrict__ adj, int n) {
    int i = blockIdx.x * blockDim.x + threadIdx.x;
    if (i < n) g_cnt[i] = 0;
    if (i == 0) {
        const long long* a = (const long long*)adj;
        int is64 = 1;
        for (int k = 0; k < 64; k++) {
            long long v = a[k];
            if (v < 0 || v > (long long)N_NODES) { is64 = 0; break; }
        }
        g_is64 = is64;
    }
}

// K2: bucket scatter — 2 edges per thread, paired index loads.
__global__ void k_scatter(const void* __restrict__ adj, int e) {
    int i = (blockIdx.x * blockDim.x + threadIdx.x) * 2;
    if (i >= e) return;

    int s0, s1, d0, d1;
    if (g_is64) {
        const long long* a = (const long long*)adj;
        longlong2 sp = *(const longlong2*)(a + i);
        longlong2 dp = *(const longlong2*)(a + e + i);
        s0 = (int)sp.x; s1 = (int)sp.y;
        d0 = (int)dp.x; d1 = (int)dp.y;
    } else {
        const int* a = (const int*)adj;
        int2 sp = *(const int2*)(a + i);
        int2 dp = *(const int2*)(a + e + i);
        s0 = sp.x; s1 = sp.y;
        d0 = dp.x; d1 = dp.y;
    }

    int p0 = atomicAdd(&g_cnt[d0], 1);
    g_esrc[(size_t)d0 * STRIDE + p0] = s0;
    if (i + 1 < e) {
        int p1 = atomicAdd(&g_cnt[d1], 1);
        g_esrc[(size_t)d1 * STRIDE + p1] = s1;
    }
}

// ---------------------------------------------------------------------------
// K3: hs = fp16( (x @ W) * rsqrt(deg+1) )  via wmma tensor cores.
// Block = 256 thr (8 warps), tile 32 rows x 128 cols. W converted to fp16
// smem ONCE per block (kills the 327MB L1 W-traffic of the FFMA versions);
// HMMA does the math. warp (wm,wn): wm in {0,1} x 16 rows, wn in {0..3} x 32
// cols (2 fragments). 8 k-steps over K=128.
__global__ void __launch_bounds__(256) k_gemm(const float* __restrict__ x,
                                              const float* __restrict__ W,
                                              int n) {
    __shared__ alignas(16) unsigned char sbuf[128 * LDH * 2 + GM_ROWS * LDH * 2];
    __half* Wsh = (__half*)sbuf;                        // 128 x LDH halfs
    __half* xsh = (__half*)(sbuf + 128 * LDH * 2);      // 32  x LDH halfs
    float*  osh = (float*)sbuf;                         // alias after mma: 32x128 f32

    const int t = threadIdx.x;
    const int block_row = blockIdx.x * GM_ROWS;

    // W (128x128 f32, row-major [k][n]) -> fp16 smem, float4 loads
    {
        const float4* Wg = (const float4*)W;
        for (int i = t; i < 128 * 32; i += 256) {       // 4096 float4
            int k = i >> 5, g = i & 31;
            float4 v = Wg[i];
            __half2 h0 = __floats2half2_rn(v.x, v.y);
            __half2 h1 = __floats2half2_rn(v.z, v.w);
            *(__half2*)(Wsh + k * LDH + g * 4)     = h0;
            *(__half2*)(Wsh + k * LDH + g * 4 + 2) = h1;
        }
    }
    // x tile (32x128) -> fp16 smem, zero-pad rows >= n
    {
        for (int i = t; i < GM_ROWS * 32; i += 256) {   // 1024 float4
            int r = i >> 5, g = i & 31;
            int row = block_row + r;
            float4 v = (row < n) ? ((const float4*)x)[(size_t)row * 32 + g]
                                 : make_float4(0.f, 0.f, 0.f, 0.f);
            __half2 h0 = __floats2half2_rn(v.x, v.y);
            __half2 h1 = __floats2half2_rn(v.z, v.w);
            *(__half2*)(xsh + r * LDH + g * 4)     = h0;
            *(__half2*)(xsh + r * LDH + g * 4 + 2) = h1;
        }
    }
    __syncthreads();

    const int wid = t >> 5;
    const int wm  = wid >> 2;       // 0..1
    const int wn  = wid & 3;        // 0..3

    wmma::fragment<wmma::accumulator, 16, 16, 16, float> acc0, acc1;
    wmma::fill_fragment(acc0, 0.0f);
    wmma::fill_fragment(acc1, 0.0f);

#pragma unroll
    for (int ks = 0; ks < 8; ks++) {
        wmma::fragment<wmma::matrix_a, 16, 16, 16, __half, wmma::row_major> a;
        wmma::fragment<wmma::matrix_b, 16, 16, 16, __half, wmma::row_major> b0, b1;
        wmma::load_matrix_sync(a,  xsh + wm * 16 * LDH + ks * 16, LDH);
        wmma::load_matrix_sync(b0, Wsh + ks * 16 * LDH + wn * 32, LDH);
        wmma::load_matrix_sync(b1, Wsh + ks * 16 * LDH + wn * 32 + 16, LDH);
        wmma::mma_sync(acc0, a, b0, acc0);
        wmma::mma_sync(acc1, a, b1, acc1);
    }
    __syncthreads();    // all Wsh/xsh reads done before aliasing as osh

    wmma::store_matrix_sync(osh + (wm * 16) * 128 + wn * 32,      acc0, 128,
                            wmma::mem_row_major);
    wmma::store_matrix_sync(osh + (wm * 16) * 128 + wn * 32 + 16, acc1, 128,
                            wmma::mem_row_major);
    __syncthreads();

    // epilogue: scale by dinv, convert fp16, store to g_hs (uint2 = 4 cols)
    for (int i = t; i < GM_ROWS * 32; i += 256) {
        int r = i >> 5, g = i & 31;
        int row = block_row + r;
        if (row < n) {
            float di = rsqrtf((float)(g_cnt[row] + 1));
            const float* src = osh + r * 128 + g * 4;
            __half2 h0 = __floats2half2_rn(src[0] * di, src[1] * di);
            __half2 h1 = __floats2half2_rn(src[2] * di, src[3] * di);
            uint2 v;
            v.x = *(unsigned*)&h0;
            v.y = *(unsigned*)&h1;
            *(uint2*)(g_hs + (size_t)row * DDIM + g * 4) = v;
        }
    }
}

// ---------------------------------------------------------------------------
__device__ __forceinline__ __half2 u2h(unsigned u) { return *(__half2*)&u; }

__device__ __forceinline__ void acc_add(float4& a, uint2 v) {
    float2 f0 = __half22float2(u2h(v.x));
    float2 f1 = __half22float2(u2h(v.y));
    a.x += f0.x; a.y += f0.y; a.z += f1.x; a.w += f1.y;
}

// K4: per-node gather (R11 proven body), 2 nodes per warp -> 5000 warps =
// single wave (R11: 10000 warps = 67/SM > 64 slots -> wave-2 tail, occ 53%).
__global__ void k_gather(const float* __restrict__ b, float* __restrict__ out,
                         int n) {
    int warp = (blockIdx.x * blockDim.x + threadIdx.x) >> 5;
    int lane = threadIdx.x & 31;
    int w0 = warp * 2;
    if (w0 >= n) return;
    int w1 = (w0 + 2 < n) ? w0 + 2 : n;

    const uint2* hs = (const uint2*)g_hs;           // 32 uint2 per row
    float4 bb = ((const float4*)b)[lane];

    for (int w = w0; w < w1; w++) {
        const int* row = g_esrc + (size_t)w * STRIDE;  // 16B-aligned
        int deg = g_cnt[w];

        float4 acc = make_float4(0.f, 0.f, 0.f, 0.f);
        acc_add(acc, hs[(size_t)w * 32 + lane]);    // self-loop term

        int kmain = deg & ~7;
        for (int k = 0; k < kmain; k += 8) {
            int4 i0 = *(const int4*)(row + k);      // uniform broadcast
            int4 i1 = *(const int4*)(row + k + 4);

            uint2 v0 = hs[(size_t)i0.x * 32 + lane];
            uint2 v1 = hs[(size_t)i0.y * 32 + lane];
            uint2 v2 = hs[(size_t)i0.z * 32 + lane];
            uint2 v3 = hs[(size_t)i0.w * 32 + lane];
            uint2 v4 = hs[(size_t)i1.x * 32 + lane];
            uint2 v5 = hs[(size_t)i1.y * 32 + lane];
            uint2 v6 = hs[(size_t)i1.z * 32 + lane];
            uint2 v7 = hs[(size_t)i1.w * 32 + lane];

            __half2 l01 = __hadd2(u2h(v0.x), u2h(v1.x));
            __half2 l23 = __hadd2(u2h(v2.x), u2h(v3.x));
            __half2 l45 = __hadd2(u2h(v4.x), u2h(v5.x));
            __half2 l67 = __hadd2(u2h(v6.x), u2h(v7.x));
            __half2 lo  = __hadd2(__hadd2(l01, l23), __hadd2(l45, l67));

            __half2 h01 = __hadd2(u2h(v0.y), u2h(v1.y));
            __half2 h23 = __hadd2(u2h(v2.y), u2h(v3.y));
            __half2 h45 = __hadd2(u2h(v4.y), u2h(v5.y));
            __half2 h67 = __hadd2(u2h(v6.y), u2h(v7.y));
            __half2 hi  = __hadd2(__hadd2(h01, h23), __hadd2(h45, h67));

            float2 fl = __half22float2(lo);
            float2 fh = __half22float2(hi);
            acc.x += fl.x; acc.y += fl.y; acc.z += fh.x; acc.w += fh.y;
        }

        for (int k = kmain; k < deg; k++) {         // tail <8, fp32 path
            int s = row[k];
            acc_add(acc, hs[(size_t)s * 32 + lane]);
        }

        float di = rsqrtf((float)(deg + 1));
        float4 o = make_float4(bb.x + di * acc.x, bb.y + di * acc.y,
                               bb.z + di * acc.z, bb.w + di * acc.w);
        ((float4*)out)[(size_t)w * 32 + lane] = o;
    }
}

// ---------------------------------------------------------------------------
extern "C" void kernel_launch(void* const* d_in, const int* in_sizes, int n_in,
                              void* d_out, int out_size) {
    const float* x   = (const float*)d_in[0];
    const void*  adj = (const void*)d_in[1];
    const float* W   = (const float*)d_in[2];
    const float* b   = (const float*)d_in[3];
    float*       out = (float*)d_out;

    int n = in_sizes[0] / DDIM;   // 10000
    int e = in_sizes[1] / 2;      // 640000

    k_init   <<<(n + 255) / 256, 256>>>(adj, n);
    int pairs = (e + 1) / 2;
    k_scatter<<<(pairs + 255) / 256, 256>>>(adj, e);
    k_gemm   <<<(n + GM_ROWS - 1) / GM_ROWS, 256>>>(x, W, n);

    long long warps_needed = ((long long)n + 1) / 2;   // 2 nodes per warp
    int blocks = (int)((warps_needed * 32 + 255) / 256);
    k_gather <<<blocks, 256>>>(b, out, n);
}